// round 14
// baseline (speedup 1.0000x reference)
#include <cuda_runtime.h>
#include <cuda_bf16.h>
#include <cstdint>

#define B_      16
#define LX_     2048
#define H_      1024
#define LOUT_   3072
#define TILE_T  16
#define SUB_T   8                   // t-rows per half (own window)
#define NTT     2                   // t-tiles per k2 block
#define NTILE   96                  // LOUT_/(TILE_T*NTT)
#define WIN     24                  // half window: slide(10) + band(14)
#define WTAB    25                  // + 1 prefix row
#define BAND    14                  // d in (-9, 5)
#define AOFF    9
#define TILE_H  512
#define CCH     8                   // prefix chunk rows
#define NCH     256                 // LX_/CCH

// kpre geometry (16 h-cols per block for load balance: 1040 blocks)
#define PHC     16
#define NHC     (H_/PHC)            // 64
#define NSL     64                  // row slices (32 rows each)
#define CPS     4                   // chunks per slice
#define C4PB    (PHC/4)             // 4 float4 columns per block

typedef unsigned long long ull;

// ---------------- device scratch (no allocs allowed) ----------------
__device__ float  g_C[(size_t)B_*NCH*H_];          // exclusive chunk prefix
__device__ float  g_n[B_];                         // valid source lengths

// ls may arrive as int64 or int32; detect at runtime.
__device__ __forceinline__ int read_ls(const void* p, int b) {
    long long v0 = ((const long long*)p)[0];
    if (v0 > 0 && v0 <= 1000000) return (int)((const long long*)p)[b];
    return ((const int*)p)[b];
}

__device__ __forceinline__ float4 f4add(float4 a, float4 b) {
    return make_float4(a.x+b.x, a.y+b.y, a.z+b.z, a.w+b.w);
}

// ---------------- kpre: fused n-count + chunk sums + chunk prefix ----------------
// grid (NHC+1, B_), 256 threads.
//   blockIdx.x <  NHC : prefix slab (16 h-cols)
//   blockIdx.x == NHC : n[b] reduction
__global__ void kpre_kernel(const float* __restrict__ z, const float* __restrict__ zm) {
    __shared__ float4 loc4[NSL*CPS*C4PB];     // 16 KB
    __shared__ float4 qtot4[NSL*C4PB];        // 4 KB
    __shared__ float4 qoff4[NSL*C4PB];        // 4 KB
    const int b = blockIdx.y;
    const int tid = threadIdx.x;

    if (blockIdx.x == NHC) {                        // kn branch
        __shared__ float red[256];
        float s = 0.f;
        for (int i = tid; i < LX_; i += 256) s += zm[b*LX_ + i];
        red[tid] = s; __syncthreads();
        for (int o = 128; o > 0; o >>= 1) {
            if (tid < o) red[tid] += red[tid + o];
            __syncthreads();
        }
        if (tid == 0) g_n[b] = red[0];
        return;
    }

    const int hb  = blockIdx.x * PHC;
    const int c4  = tid & (C4PB-1);                 // float4 column 0..3
    const int sl  = tid >> 2;                       // row slice 0..63 (32 rows)

    // pass A: chunk-local exclusive sums within this slice (single z read)
    const float4* src = (const float4*)(z + ((size_t)(b*LX_ + sl*32))*H_ + hb) + c4;
    float4 run = make_float4(0.f, 0.f, 0.f, 0.f);
    for (int k = 0; k < CPS; k++) {
        loc4[(sl*CPS + k)*C4PB + c4] = run;
        float4 v[CCH];
        #pragma unroll
        for (int j = 0; j < CCH; j++) v[j] = src[(size_t)(k*CCH + j)*(H_/4)];
        #pragma unroll
        for (int j = 0; j < CCH; j++) run = f4add(run, v[j]);
    }
    qtot4[sl*C4PB + c4] = run;
    __syncthreads();

    // serial exclusive prefix over the 64 slices (one thread per f4 column)
    if (tid < C4PB) {
        float4 off = make_float4(0.f, 0.f, 0.f, 0.f);
        for (int s2 = 0; s2 < NSL; s2++) {
            qoff4[s2*C4PB + tid] = off;
            off = f4add(off, qtot4[s2*C4PB + tid]);
        }
    }
    __syncthreads();

    // pass B: emit global exclusive chunk prefix
    float4 off = qoff4[sl*C4PB + c4];
    float4* dst = (float4*)(g_C + ((size_t)(b*NCH + sl*CPS))*H_ + hb) + c4;
    for (int k = 0; k < CPS; k++)
        dst[(size_t)k*(H_/4)] = f4add(off, loc4[(sl*CPS + k)*C4PB + c4]);
}

// ---------------- k2: fused weights + banded weighted sum, dual windows ----------
// f32x2 lanes hold a t-PAIR: weights come packed for free from consecutive smem
// floats; z is duplicated in-register (movs reused by all 4 t-pairs).
// Each block processes NTT=2 t-tiles sequentially (amortizes ramp + waves).
__device__ __forceinline__ void fma2(ull &acc, ull a, ull b) {
    asm volatile("fma.rn.f32x2 %0, %1, %2, %0;" : "+l"(acc) : "l"(a), "l"(b));
}
__device__ __forceinline__ ull dupf2(float v) {
    ull r;
    asm("mov.b64 %0, {%1,%1};" : "=l"(r) : "f"(v));
    return r;
}

#define PFD 3   // register prefetch depth (full unroll const-folds rotation)

__global__ __launch_bounds__(256, 4) void k2_kernel(const float* __restrict__ z,
                                                    const void* __restrict__ lsp,
                                                    const float* __restrict__ sigma,
                                                    float* __restrict__ out,
                                                    float* __restrict__ outm) {
    __shared__ __align__(16) float ws[2][WTAB][SUB_T];   // scalar weights
    __shared__ float s_mu[TILE_T], s_ps[TILE_T];
    __shared__ int   s_a[TILE_T], s_A[2];

    const int hb = blockIdx.x * TILE_H;
    const int b = blockIdx.z;
    const int tid = threadIdx.x;
    const int tsub = tid >> 7;    // 0..1 : which 8-t half (own window)
    const int hq   = tid & 127;   // 0..127: which 4-h group

    const float nf = g_n[b];
    const int   n  = (int)(nf + 0.5f);
    const float* zcol = z + (size_t)b*LX_*H_ + hb + hq*4;

    #pragma unroll 1
    for (int tt = 0; tt < NTT; tt++) {
        const int tileIdx = blockIdx.y*NTT + tt;

        // --- per-t meta: mu, a, 1/denominator ---
        if (tid < TILE_T) {
            const int lsb = read_ls(lsp, b);
            const float sg = sigma[0];
            const float c  = 0.5f / (sg*sg);
            int t = tileIdx*TILE_T + tid;
            float mu = (float)t * nf / (float)lsb;   // bit-exact vs reference
            int a = (int)ceilf(mu) - AOFF;
            a = a < 0 ? 0 : (a > n ? n : a);
            float sum = (float)a;                    // rows below band have weight ~1
            #pragma unroll
            for (int j = 0; j < BAND; j++) {
                int s = a + j;
                if (s < n) sum += __expf(-c * exp2f((float)s - mu));
            }
            float m = (t < lsb) ? 1.0f : 0.0f;
            s_ps[tid] = m / sum;
            s_mu[tid] = mu; s_a[tid] = a;
            if (blockIdx.x == 0) outm[b*LOUT_ + t] = m;  // output mask (fused)
            if ((tid & (SUB_T-1)) == 0) {            // first t of each half
                int A = a;
                if (A > n - WIN) A = n - WIN;
                if (A < 0) A = 0;
                s_A[tid >> 3] = A;
            }
        }
        __syncthreads();

        const int A = s_A[tsub];

        // start z prefetch pipeline early (overlaps weight-table exps)
        float4 zr[PFD];
        #pragma unroll
        for (int d = 0; d < PFD; d++) {
            int r = A + d; if (r > LX_-1) r = LX_-1;
            zr[d] = *(const float4*)(zcol + (size_t)r*H_);
        }

        // reconstruct prefix row P[A] = Cpref[A>>3] + residual z rows [8c, A)
        float4 p4;
        {
            int c8 = A >> 3, r0 = c8 << 3;
            p4 = *(const float4*)(g_C + ((size_t)(b*NCH + c8))*H_ + hb + hq*4);
            for (int r = r0; r < A; r++) {
                float4 v = *(const float4*)(zcol + (size_t)r*H_);
                p4.x += v.x; p4.y += v.y; p4.z += v.z; p4.w += v.w;
            }
        }

        // --- fill weight tables: 2*WTAB*SUB_T = 400 scalar entries ---
        {
            const float sg = sigma[0];
            const float c  = 0.5f / (sg*sg);
            for (int idx = tid; idx < 2*WTAB*SUB_T; idx += 256) {
                int sb = idx / (WTAB*SUB_T);
                int rem = idx - sb*(WTAB*SUB_T);
                int u = rem >> 3, t = rem & (SUB_T-1);
                int tt2 = sb*SUB_T + t;
                int Ab = s_A[sb];
                float w;
                if (u == 0) w = s_ps[tt2];           // coefficient for P[A]
                else {
                    int s = Ab + u - 1;
                    if (s < s_a[tt2]) w = s_ps[tt2]; // bridge row: weight 1 * inv_denom
                    else if (s < s_a[tt2] + BAND && s < n)
                        w = s_ps[tt2] * __expf(-c * exp2f((float)s - s_mu[tt2]));
                    else w = 0.0f;
                }
                ws[sb][u][t] = w;
            }
        }

        // acc[h][tp]: h = 0..3 (4 h-cols), tp = 0..3 (t-pairs 01,23,45,67)
        ull acc[4][4];
        #pragma unroll
        for (int i = 0; i < 4; i++)
            #pragma unroll
            for (int j = 0; j < 4; j++) acc[i][j] = 0ull;

        __syncthreads();   // ws visible

        // u = 0: prefix row
        {
            ulonglong2 wv0 = *(const ulonglong2*)&ws[tsub][0][0];
            ulonglong2 wv1 = *(const ulonglong2*)&ws[tsub][0][4];
            ull zd0 = dupf2(p4.x), zd1 = dupf2(p4.y), zd2 = dupf2(p4.z), zd3 = dupf2(p4.w);
            fma2(acc[0][0], zd0, wv0.x); fma2(acc[0][1], zd0, wv0.y);
            fma2(acc[0][2], zd0, wv1.x); fma2(acc[0][3], zd0, wv1.y);
            fma2(acc[1][0], zd1, wv0.x); fma2(acc[1][1], zd1, wv0.y);
            fma2(acc[1][2], zd1, wv1.x); fma2(acc[1][3], zd1, wv1.y);
            fma2(acc[2][0], zd2, wv0.x); fma2(acc[2][1], zd2, wv0.y);
            fma2(acc[2][2], zd2, wv1.x); fma2(acc[2][3], zd2, wv1.y);
            fma2(acc[3][0], zd3, wv0.x); fma2(acc[3][1], zd3, wv0.y);
            fma2(acc[3][2], zd3, wv1.x); fma2(acc[3][3], zd3, wv1.y);
        }

        #pragma unroll
        for (int u = 0; u < WIN; u++) {
            float4 cur = zr[u % PFD];
            int pf = A + u + PFD; if (pf > LX_-1) pf = LX_-1;  // tail prefetch unused
            zr[u % PFD] = *(const float4*)(zcol + (size_t)pf*H_);
            ulonglong2 wv0 = *(const ulonglong2*)&ws[tsub][u+1][0];
            ulonglong2 wv1 = *(const ulonglong2*)&ws[tsub][u+1][4];
            ull zd0 = dupf2(cur.x), zd1 = dupf2(cur.y), zd2 = dupf2(cur.z), zd3 = dupf2(cur.w);
            fma2(acc[0][0], zd0, wv0.x); fma2(acc[0][1], zd0, wv0.y);
            fma2(acc[0][2], zd0, wv1.x); fma2(acc[0][3], zd0, wv1.y);
            fma2(acc[1][0], zd1, wv0.x); fma2(acc[1][1], zd1, wv0.y);
            fma2(acc[1][2], zd1, wv1.x); fma2(acc[1][3], zd1, wv1.y);
            fma2(acc[2][0], zd2, wv0.x); fma2(acc[2][1], zd2, wv0.y);
            fma2(acc[2][2], zd2, wv1.x); fma2(acc[2][3], zd2, wv1.y);
            fma2(acc[3][0], zd3, wv0.x); fma2(acc[3][1], zd3, wv0.y);
            fma2(acc[3][2], zd3, wv1.x); fma2(acc[3][3], zd3, wv1.y);
        }

        // epilogue: unpack t-pairs -> per-t float4 stores (8t x 4h per thread)
        const int tg = tileIdx*TILE_T + tsub*SUB_T;
        float* ob = out + ((size_t)b*LOUT_ + tg)*H_ + hb + hq*4;
        #pragma unroll
        for (int tp = 0; tp < 4; tp++) {
            float4 r0, r1;
            asm volatile("mov.b64 {%0,%1}, %2;" : "=f"(r0.x), "=f"(r1.x) : "l"(acc[0][tp]));
            asm volatile("mov.b64 {%0,%1}, %2;" : "=f"(r0.y), "=f"(r1.y) : "l"(acc[1][tp]));
            asm volatile("mov.b64 {%0,%1}, %2;" : "=f"(r0.z), "=f"(r1.z) : "l"(acc[2][tp]));
            asm volatile("mov.b64 {%0,%1}, %2;" : "=f"(r0.w), "=f"(r1.w) : "l"(acc[3][tp]));
            *(float4*)(ob + (size_t)(2*tp)*H_)   = r0;
            *(float4*)(ob + (size_t)(2*tp+1)*H_) = r1;
        }
        __syncthreads();   // all warps done with ws/s_* before next tile rewrites
    }
}

// ---------------- launch ----------------
extern "C" void kernel_launch(void* const* d_in, const int* in_sizes, int n_in,
                              void* d_out, int out_size) {
    const float* z     = (const float*)d_in[0];
    const void*  ls    = d_in[1];
    const float* zmask = (const float*)d_in[2];
    const float* sigma = (const float*)d_in[3];
    float* out  = (float*)d_out;
    float* outm = out + (size_t)B_*LOUT_*H_;

    kpre_kernel<<<dim3(NHC + 1, B_), 256>>>(z, zmask);
    k2_kernel<<<dim3(2, NTILE, B_), 256>>>(z, ls, sigma, out, outm);
}

// round 15
// speedup vs baseline: 1.0031x; 1.0031x over previous
#include <cuda_runtime.h>
#include <cuda_bf16.h>
#include <cstdint>

#define B_      16
#define LX_     2048
#define H_      1024
#define LOUT_   3072
#define TILE_T  16
#define SUB_T   8                   // t-rows per half (own window)
#define NTILE   192                 // LOUT_/TILE_T
#define WIN     24                  // half window: slide(10) + band(14)
#define WTAB    25                  // + 1 prefix row
#define BAND    14                  // d in (-9, 5)
#define AOFF    9
#define TILE_H  512
#define CCH     8                   // prefix chunk rows
#define NCH     256                 // LX_/CCH

// kpre geometry (R13: 64 h-cols/block, warp reads 512B contiguous)
#define PHC     64
#define NHC     (H_/PHC)            // 16
#define NSL     16                  // row slices (128 rows each)
#define CPS     16                  // chunks per slice
#define KPRE_SMEM ((NSL*CPS*16 + 2*NSL*16) * 16)   // 73728 B

typedef unsigned long long ull;

// ---------------- device scratch (no allocs allowed) ----------------
__device__ float  g_C[(size_t)B_*NCH*H_];          // exclusive chunk prefix
__device__ float  g_n[B_];                         // valid source lengths

// ls may arrive as int64 or int32; detect at runtime.
__device__ __forceinline__ int read_ls(const void* p, int b) {
    long long v0 = ((const long long*)p)[0];
    if (v0 > 0 && v0 <= 1000000) return (int)((const long long*)p)[b];
    return ((const int*)p)[b];
}

__device__ __forceinline__ float4 f4add(float4 a, float4 b) {
    return make_float4(a.x+b.x, a.y+b.y, a.z+b.z, a.w+b.w);
}

// ---------------- kpre: fused n-count + chunk sums + chunk prefix ----------------
// grid (NHC+1, B_), 256 threads, KPRE_SMEM dynamic.
//   blockIdx.x <  NHC : prefix slab (64 h-cols)
//   blockIdx.x == NHC : n[b] reduction
__global__ void kpre_kernel(const float* __restrict__ z, const float* __restrict__ zm) {
    extern __shared__ float4 s4[];
    const int b = blockIdx.y;
    const int tid = threadIdx.x;

    if (blockIdx.x == NHC) {                        // kn branch
        float* red = (float*)s4;
        float s = 0.f;
        for (int i = tid; i < LX_; i += 256) s += zm[b*LX_ + i];
        red[tid] = s; __syncthreads();
        for (int o = 128; o > 0; o >>= 1) {
            if (tid < o) red[tid] += red[tid + o];
            __syncthreads();
        }
        if (tid == 0) g_n[b] = red[0];
        return;
    }

    float4* loc4  = s4;                             // [NSL*CPS][16]
    float4* qtot4 = s4 + NSL*CPS*16;                // [NSL][16]
    float4* qoff4 = qtot4 + NSL*16;                 // [NSL][16]

    const int hb  = blockIdx.x * PHC;
    const int c4  = tid & 15;                       // float4 column
    const int sl  = tid >> 4;                       // row slice 0..15 (128 rows)

    // pass A: chunk-local exclusive sums within this slice (single z read)
    const float4* src = (const float4*)(z + ((size_t)(b*LX_ + sl*128))*H_ + hb) + c4;
    float4 run = make_float4(0.f, 0.f, 0.f, 0.f);
    for (int k = 0; k < CPS; k++) {
        loc4[(sl*CPS + k)*16 + c4] = run;
        float4 v[CCH];
        #pragma unroll
        for (int j = 0; j < CCH; j++) v[j] = src[(size_t)(k*CCH + j)*(H_/4)];
        #pragma unroll
        for (int j = 0; j < CCH; j++) run = f4add(run, v[j]);
    }
    qtot4[sl*16 + c4] = run;
    __syncthreads();

    // serial exclusive prefix over the 16 slices (one thread per column)
    if (tid < 16) {
        float4 off = make_float4(0.f, 0.f, 0.f, 0.f);
        for (int s2 = 0; s2 < NSL; s2++) {
            qoff4[s2*16 + tid] = off;
            off = f4add(off, qtot4[s2*16 + tid]);
        }
    }
    __syncthreads();

    // pass B: emit global exclusive chunk prefix (16 MB total)
    float4 off = qoff4[sl*16 + c4];
    float4* dst = (float4*)(g_C + ((size_t)(b*NCH + sl*CPS))*H_ + hb) + c4;
    for (int k = 0; k < CPS; k++)
        dst[(size_t)k*(H_/4)] = f4add(off, loc4[(sl*CPS + k)*16 + c4]);
}

// ---------------- k2: fused weights + banded weighted sum, dual windows ----------
// f32x2 lanes hold a t-PAIR: weights come packed for free from consecutive smem
// floats; z is duplicated in-register (movs reused by all 4 t-pairs).
__device__ __forceinline__ void fma2(ull &acc, ull a, ull b) {
    asm volatile("fma.rn.f32x2 %0, %1, %2, %0;" : "+l"(acc) : "l"(a), "l"(b));
}
__device__ __forceinline__ ull dupf2(float v) {
    ull r;
    asm("mov.b64 %0, {%1,%1};" : "=l"(r) : "f"(v));
    return r;
}

#define PFD 3   // register prefetch depth (full unroll const-folds rotation)

__global__ __launch_bounds__(256, 4) void k2_kernel(const float* __restrict__ z,
                                                    const void* __restrict__ lsp,
                                                    const float* __restrict__ sigma,
                                                    float* __restrict__ out,
                                                    float* __restrict__ outm) {
    __shared__ __align__(16) float ws[2][WTAB][SUB_T];   // scalar weights
    __shared__ float s_mu[TILE_T], s_ps[TILE_T];
    __shared__ int   s_a[TILE_T], s_A[2];

    const int hb = blockIdx.x * TILE_H;
    const int tileInB = blockIdx.y;
    const int b = blockIdx.z;
    const int tid = threadIdx.x;
    const int tsub = tid >> 7;    // 0..1 : which 8-t half (own window)
    const int hq   = tid & 127;   // 0..127: which 4-h group

    const float nf = g_n[b];
    const int   n  = (int)(nf + 0.5f);

    // --- per-t meta: mu, a, 1/denominator ---
    if (tid < TILE_T) {
        const int lsb = read_ls(lsp, b);
        const float sg = sigma[0];
        const float c  = 0.5f / (sg*sg);
        int t = tileInB*TILE_T + tid;
        float mu = (float)t * nf / (float)lsb;       // bit-exact vs reference
        int a = (int)ceilf(mu) - AOFF;
        a = a < 0 ? 0 : (a > n ? n : a);
        float sum = (float)a;                        // rows below band have weight ~1
        #pragma unroll
        for (int j = 0; j < BAND; j++) {
            int s = a + j;
            if (s < n) sum += __expf(-c * exp2f((float)s - mu));
        }
        float m = (t < lsb) ? 1.0f : 0.0f;
        s_ps[tid] = m / sum;
        s_mu[tid] = mu; s_a[tid] = a;
        if (blockIdx.x == 0) outm[b*LOUT_ + t] = m;  // output mask (fused)
        if ((tid & (SUB_T-1)) == 0) {                // first t of each half
            int A = a;
            if (A > n - WIN) A = n - WIN;
            if (A < 0) A = 0;
            s_A[tid >> 3] = A;
        }
    }
    __syncthreads();

    const int A = s_A[tsub];
    const float* zcol = z + (size_t)b*LX_*H_ + hb + hq*4;

    // start z prefetch pipeline early (overlaps weight-table exps)
    float4 zr[PFD];
    #pragma unroll
    for (int d = 0; d < PFD; d++) {
        int r = A + d; if (r > LX_-1) r = LX_-1;
        zr[d] = *(const float4*)(zcol + (size_t)r*H_);
    }

    // reconstruct prefix row P[A] = Cpref[A>>3] + residual z rows [8c, A)
    float4 p4;
    {
        int c8 = A >> 3, r0 = c8 << 3;
        p4 = *(const float4*)(g_C + ((size_t)(b*NCH + c8))*H_ + hb + hq*4);
        for (int r = r0; r < A; r++) {
            float4 v = *(const float4*)(zcol + (size_t)r*H_);
            p4.x += v.x; p4.y += v.y; p4.z += v.z; p4.w += v.w;
        }
    }

    // --- fill weight tables: 2*WTAB*SUB_T = 400 scalar entries ---
    {
        const float sg = sigma[0];
        const float c  = 0.5f / (sg*sg);
        for (int idx = tid; idx < 2*WTAB*SUB_T; idx += 256) {
            int sb = idx / (WTAB*SUB_T);
            int rem = idx - sb*(WTAB*SUB_T);
            int u = rem >> 3, t = rem & (SUB_T-1);
            int tt = sb*SUB_T + t;
            int Ab = s_A[sb];
            float w;
            if (u == 0) w = s_ps[tt];                // coefficient for P[A]
            else {
                int s = Ab + u - 1;
                if (s < s_a[tt]) w = s_ps[tt];       // bridge row: weight 1 * inv_denom
                else if (s < s_a[tt] + BAND && s < n)
                    w = s_ps[tt] * __expf(-c * exp2f((float)s - s_mu[tt]));
                else w = 0.0f;
            }
            ws[sb][u][t] = w;
        }
    }

    // acc[h][tp]: h = 0..3 (this thread's 4 h-cols), tp = 0..3 (t-pairs 01,23,45,67)
    ull acc[4][4];
    #pragma unroll
    for (int i = 0; i < 4; i++)
        #pragma unroll
        for (int j = 0; j < 4; j++) acc[i][j] = 0ull;

    __syncthreads();   // ws visible

    // u = 0: prefix row
    {
        ulonglong2 wv0 = *(const ulonglong2*)&ws[tsub][0][0];  // (w0,w1),(w2,w3)
        ulonglong2 wv1 = *(const ulonglong2*)&ws[tsub][0][4];  // (w4,w5),(w6,w7)
        ull zd0 = dupf2(p4.x), zd1 = dupf2(p4.y), zd2 = dupf2(p4.z), zd3 = dupf2(p4.w);
        fma2(acc[0][0], zd0, wv0.x); fma2(acc[0][1], zd0, wv0.y);
        fma2(acc[0][2], zd0, wv1.x); fma2(acc[0][3], zd0, wv1.y);
        fma2(acc[1][0], zd1, wv0.x); fma2(acc[1][1], zd1, wv0.y);
        fma2(acc[1][2], zd1, wv1.x); fma2(acc[1][3], zd1, wv1.y);
        fma2(acc[2][0], zd2, wv0.x); fma2(acc[2][1], zd2, wv0.y);
        fma2(acc[2][2], zd2, wv1.x); fma2(acc[2][3], zd2, wv1.y);
        fma2(acc[3][0], zd3, wv0.x); fma2(acc[3][1], zd3, wv0.y);
        fma2(acc[3][2], zd3, wv1.x); fma2(acc[3][3], zd3, wv1.y);
    }

    #pragma unroll
    for (int u = 0; u < WIN; u++) {
        float4 cur = zr[u % PFD];
        int pf = A + u + PFD; if (pf > LX_-1) pf = LX_-1;   // tail prefetch never consumed
        zr[u % PFD] = *(const float4*)(zcol + (size_t)pf*H_);
        ulonglong2 wv0 = *(const ulonglong2*)&ws[tsub][u+1][0];
        ulonglong2 wv1 = *(const ulonglong2*)&ws[tsub][u+1][4];
        ull zd0 = dupf2(cur.x), zd1 = dupf2(cur.y), zd2 = dupf2(cur.z), zd3 = dupf2(cur.w);
        fma2(acc[0][0], zd0, wv0.x); fma2(acc[0][1], zd0, wv0.y);
        fma2(acc[0][2], zd0, wv1.x); fma2(acc[0][3], zd0, wv1.y);
        fma2(acc[1][0], zd1, wv0.x); fma2(acc[1][1], zd1, wv0.y);
        fma2(acc[1][2], zd1, wv1.x); fma2(acc[1][3], zd1, wv1.y);
        fma2(acc[2][0], zd2, wv0.x); fma2(acc[2][1], zd2, wv0.y);
        fma2(acc[2][2], zd2, wv1.x); fma2(acc[2][3], zd2, wv1.y);
        fma2(acc[3][0], zd3, wv0.x); fma2(acc[3][1], zd3, wv0.y);
        fma2(acc[3][2], zd3, wv1.x); fma2(acc[3][3], zd3, wv1.y);
    }

    // epilogue: unpack t-pairs -> per-t float4 stores (8t x 4h per thread)
    const int tg = tileInB*TILE_T + tsub*SUB_T;
    float* ob = out + ((size_t)b*LOUT_ + tg)*H_ + hb + hq*4;
    #pragma unroll
    for (int tp = 0; tp < 4; tp++) {
        float4 r0, r1;
        asm volatile("mov.b64 {%0,%1}, %2;" : "=f"(r0.x), "=f"(r1.x) : "l"(acc[0][tp]));
        asm volatile("mov.b64 {%0,%1}, %2;" : "=f"(r0.y), "=f"(r1.y) : "l"(acc[1][tp]));
        asm volatile("mov.b64 {%0,%1}, %2;" : "=f"(r0.z), "=f"(r1.z) : "l"(acc[2][tp]));
        asm volatile("mov.b64 {%0,%1}, %2;" : "=f"(r0.w), "=f"(r1.w) : "l"(acc[3][tp]));
        *(float4*)(ob + (size_t)(2*tp)*H_)   = r0;
        *(float4*)(ob + (size_t)(2*tp+1)*H_) = r1;
    }
}

// ---------------- launch ----------------
extern "C" void kernel_launch(void* const* d_in, const int* in_sizes, int n_in,
                              void* d_out, int out_size) {
    const float* z     = (const float*)d_in[0];
    const void*  ls    = d_in[1];
    const float* zmask = (const float*)d_in[2];
    const float* sigma = (const float*)d_in[3];
    float* out  = (float*)d_out;
    float* outm = out + (size_t)B_*LOUT_*H_;

    cudaFuncSetAttribute(kpre_kernel, cudaFuncAttributeMaxDynamicSharedMemorySize, KPRE_SMEM);

    kpre_kernel<<<dim3(NHC + 1, B_), 256, KPRE_SMEM>>>(z, zmask);
    k2_kernel<<<dim3(2, NTILE, B_), 256>>>(z, ls, sigma, out, outm);
}